// round 14
// baseline (speedup 1.0000x reference)
#include <cuda_runtime.h>
#include <cuda_fp16.h>
#include <cuda_bf16.h>
#include <math.h>
#include <stdint.h>

#define V 50257
#define D 128
#define B 1024
#define C 10
#define TWO_D 256
#define NB 4                 // batch rows per encoder CTA
#define NROW (NB * C)        // 40 cx rows per CTA

// vocab GEMM tiling (fp16 mma.sync m16n8k16)
#define M_CTA 128
#define N_CTA 128
#define KT 32
#define WS_STRIDE 136
#define WS_BUF (16 * WS_STRIDE)
#define NCHUNK ((V + N_CTA - 1) / N_CTA)   // 393
#define FIN_BLOCKS (B / 4)

// encoder smem layout (floats)
#define EO_A      0            // A_s   [40*128] = 5120
#define EO_CE     5120         // ce_s  [4*128]  = 512
#define EO_CP     5632         // cepart[4*256]  = 1024
#define EO_B      6656         // B_s   [16*256] = 4096 (main loop)  -> ends 10752
#define EO_HW     6656         // hw_s  [8*256]  = 2048 (post, aliases B)
#define EO_H      8704         // h_s   [4*256]  = 1024 (post, aliases B)
#define EO_MEAN   0            // mean_s[4*128]  = 512  (post, aliases A)
#define EO_VAR    512          // var_s [4*128]  = 512  (post, aliases A)
#define EO_TOTAL  10752

// ---------------- scratch ----------------
__device__ float              g_z[B * D];
__device__ unsigned           g_zh2[B * D / 2];
__device__ float              g_kl[B];
__device__ float              g_pmax[B * NCHUNK];
__device__ float              g_psum[B * NCHUNK];
__device__ long long          g_acc;
__device__ unsigned int       g_done;

__device__ __forceinline__ float softplus_f(float x) {
    return fmaxf(x, 0.f) + log1pf(expf(-fabsf(x)));
}

__device__ __forceinline__ void mma_f16(float c[4],
                                        unsigned a0, unsigned a1, unsigned a2, unsigned a3,
                                        unsigned b0, unsigned b1) {
    asm volatile(
        "mma.sync.aligned.m16n8k16.row.col.f32.f16.f16.f32 "
        "{%0,%1,%2,%3}, {%4,%5,%6,%7}, {%8,%9}, {%0,%1,%2,%3};"
        : "+f"(c[0]), "+f"(c[1]), "+f"(c[2]), "+f"(c[3])
        : "r"(a0), "r"(a1), "r"(a2), "r"(a3), "r"(b0), "r"(b1));
}

// ---------------- kernel 1: register-tiled encoder + heads + KL + z ----------------
// cx GEMM [40,128]@[128,256]: 8 warps x 5 rows; thread = 5 rows x (4+4) cols.
__global__ void __launch_bounds__(256) encoder_kernel(
    const int* __restrict__ center_id, const int* __restrict__ context_ids,
    const float* __restrict__ epsilon, const float* __restrict__ emb,
    const float* __restrict__ prior_means, const float* __restrict__ prior_vars,
    const float* __restrict__ W_enc, const float* __restrict__ b_enc,
    const float* __restrict__ W_mean, const float* __restrict__ b_mean,
    const float* __restrict__ W_var, const float* __restrict__ b_var)
{
    __shared__ float S[EO_TOTAL];
    __shared__ int   ctx_s[NROW];
    __shared__ int   cid_s[NB];
    __shared__ float red_s[NB][4];

    const int b0   = blockIdx.x * NB;
    const int tid  = threadIdx.x;
    const int lane = tid & 31;
    const int w    = tid >> 5;
    const int l4   = lane * 4;

    if (blockIdx.x == 0 && tid == 0) { g_acc = 0ll; g_done = 0u; }

    if (tid < NB)   cid_s[tid] = center_id[b0 + tid];
    if (tid < NROW) ctx_s[tid] = context_ids[b0 * C + tid];
    __syncthreads();

    // gather ce (4x128) and A = cx (40x128), float4-coalesced
    if (tid < NB * 32) {
        int row = tid >> 5, l = tid & 31;
        *(float4*)&S[EO_CE + row * D + l * 4] =
            *(const float4*)&emb[cid_s[row] * D + l * 4];
    }
    for (int e = tid; e < NROW * 32; e += 256) {
        int row = e >> 5, l = e & 31;
        *(float4*)&S[EO_A + row * D + l * 4] =
            *(const float4*)&emb[ctx_s[row] * D + l * 4];
    }
    __syncthreads();

    // cepart[nb][j] = ce_nb . W1[:,j]  (j = tid); float4 h-reads + MLP-8 W loads
    {
        const int j = tid;
        float cp[NB] = {0.f, 0.f, 0.f, 0.f};
        #pragma unroll 2
        for (int k = 0; k < D; k += 4) {
            float4 c0 = *(float4*)&S[EO_CE + 0 * D + k];
            float4 c1 = *(float4*)&S[EO_CE + 1 * D + k];
            float4 c2 = *(float4*)&S[EO_CE + 2 * D + k];
            float4 c3 = *(float4*)&S[EO_CE + 3 * D + k];
            float w0 = W_enc[(k + 0) * TWO_D + j];
            float w1 = W_enc[(k + 1) * TWO_D + j];
            float w2 = W_enc[(k + 2) * TWO_D + j];
            float w3 = W_enc[(k + 3) * TWO_D + j];
            cp[0] = fmaf(c0.x, w0, cp[0]); cp[0] = fmaf(c0.y, w1, cp[0]);
            cp[0] = fmaf(c0.z, w2, cp[0]); cp[0] = fmaf(c0.w, w3, cp[0]);
            cp[1] = fmaf(c1.x, w0, cp[1]); cp[1] = fmaf(c1.y, w1, cp[1]);
            cp[1] = fmaf(c1.z, w2, cp[1]); cp[1] = fmaf(c1.w, w3, cp[1]);
            cp[2] = fmaf(c2.x, w0, cp[2]); cp[2] = fmaf(c2.y, w1, cp[2]);
            cp[2] = fmaf(c2.z, w2, cp[2]); cp[2] = fmaf(c2.w, w3, cp[2]);
            cp[3] = fmaf(c3.x, w0, cp[3]); cp[3] = fmaf(c3.y, w1, cp[3]);
            cp[3] = fmaf(c3.z, w2, cp[3]); cp[3] = fmaf(c3.w, w3, cp[3]);
        }
        #pragma unroll
        for (int nb = 0; nb < NB; nb++) S[EO_CP + nb * TWO_D + j] = cp[nb];
    }

    // ---- main cx GEMM, W2 staged in 16-k tiles, register prefetch ----
    float acc[5][8];
    #pragma unroll
    for (int i = 0; i < 5; i++)
        #pragma unroll
        for (int j = 0; j < 8; j++) acc[i][j] = 0.f;

    const float* W2 = W_enc + D * TWO_D;
    float4 pf[4];
    #pragma unroll
    for (int i = 0; i < 4; i++)
        pf[i] = *(const float4*)(W2 + tid * 4 + i * 1024);

    const int arow = w * 5 * D;
    #pragma unroll 1
    for (int kt = 0; kt < 8; kt++) {
        __syncthreads();                       // B_s readers from prev iter done
        #pragma unroll
        for (int i = 0; i < 4; i++)
            *(float4*)&S[EO_B + tid * 4 + i * 1024] = pf[i];
        __syncthreads();
        if (kt < 7) {
            #pragma unroll
            for (int i = 0; i < 4; i++)
                pf[i] = *(const float4*)(W2 + (kt + 1) * 4096 + tid * 4 + i * 1024);
        }
        const int kb = kt * 16;
        #pragma unroll
        for (int kk = 0; kk < 16; kk++) {
            float4 bv0 = *(float4*)&S[EO_B + kk * TWO_D + l4];
            float4 bv1 = *(float4*)&S[EO_B + kk * TWO_D + 128 + l4];
            #pragma unroll
            for (int i = 0; i < 5; i++) {
                float a = S[EO_A + arow + i * D + kb + kk];
                acc[i][0] = fmaf(a, bv0.x, acc[i][0]);
                acc[i][1] = fmaf(a, bv0.y, acc[i][1]);
                acc[i][2] = fmaf(a, bv0.z, acc[i][2]);
                acc[i][3] = fmaf(a, bv0.w, acc[i][3]);
                acc[i][4] = fmaf(a, bv1.x, acc[i][4]);
                acc[i][5] = fmaf(a, bv1.y, acc[i][5]);
                acc[i][6] = fmaf(a, bv1.z, acc[i][6]);
                acc[i][7] = fmaf(a, bv1.w, acc[i][7]);
            }
        }
    }
    __syncthreads();    // all B_s reads done before hw_s (aliased) writes

    // ---- epilogue: relu(acc + cepart + b_enc), sum over 5 rows -> warp partial ----
    {
        const int nb = w >> 1;
        float4 cp0 = *(float4*)&S[EO_CP + nb * TWO_D + l4];
        float4 cp1 = *(float4*)&S[EO_CP + nb * TWO_D + 128 + l4];
        float4 be0 = *(const float4*)&b_enc[l4];
        float4 be1 = *(const float4*)&b_enc[128 + l4];
        float hp[8];
        #pragma unroll
        for (int j = 0; j < 8; j++) hp[j] = 0.f;
        #pragma unroll
        for (int i = 0; i < 5; i++) {
            hp[0] += fmaxf(acc[i][0] + cp0.x + be0.x, 0.f);
            hp[1] += fmaxf(acc[i][1] + cp0.y + be0.y, 0.f);
            hp[2] += fmaxf(acc[i][2] + cp0.z + be0.z, 0.f);
            hp[3] += fmaxf(acc[i][3] + cp0.w + be0.w, 0.f);
            hp[4] += fmaxf(acc[i][4] + cp1.x + be1.x, 0.f);
            hp[5] += fmaxf(acc[i][5] + cp1.y + be1.y, 0.f);
            hp[6] += fmaxf(acc[i][6] + cp1.z + be1.z, 0.f);
            hp[7] += fmaxf(acc[i][7] + cp1.w + be1.w, 0.f);
        }
        *(float4*)&S[EO_HW + w * TWO_D + l4]       = make_float4(hp[0], hp[1], hp[2], hp[3]);
        *(float4*)&S[EO_HW + w * TWO_D + 128 + l4] = make_float4(hp[4], hp[5], hp[6], hp[7]);
    }
    __syncthreads();
    // combine warp pairs -> h[nb][j]
    for (int e = tid; e < NB * TWO_D; e += 256) {
        int nb = e >> 8, j = e & 255;
        S[EO_H + e] = S[EO_HW + (2 * nb) * TWO_D + j] + S[EO_HW + (2 * nb + 1) * TWO_D + j];
    }
    __syncthreads();

    // ---- heads: mean (threads 0..127), softplus(var) (threads 128..255) ----
    // float4 h-reads + 4 independent W loads per step, unroll 2 -> MLP ~8
    if (tid < D) {
        int d = tid;
        float m0 = b_mean[d], m1 = m0, m2 = m0, m3 = m0;
        #pragma unroll 2
        for (int k = 0; k < TWO_D; k += 4) {
            float4 h0 = *(float4*)&S[EO_H + 0 * TWO_D + k];
            float4 h1 = *(float4*)&S[EO_H + 1 * TWO_D + k];
            float4 h2 = *(float4*)&S[EO_H + 2 * TWO_D + k];
            float4 h3 = *(float4*)&S[EO_H + 3 * TWO_D + k];
            float w0 = W_mean[(k + 0) * D + d];
            float w1 = W_mean[(k + 1) * D + d];
            float w2 = W_mean[(k + 2) * D + d];
            float w3 = W_mean[(k + 3) * D + d];
            m0 = fmaf(h0.x, w0, m0); m0 = fmaf(h0.y, w1, m0);
            m0 = fmaf(h0.z, w2, m0); m0 = fmaf(h0.w, w3, m0);
            m1 = fmaf(h1.x, w0, m1); m1 = fmaf(h1.y, w1, m1);
            m1 = fmaf(h1.z, w2, m1); m1 = fmaf(h1.w, w3, m1);
            m2 = fmaf(h2.x, w0, m2); m2 = fmaf(h2.y, w1, m2);
            m2 = fmaf(h2.z, w2, m2); m2 = fmaf(h2.w, w3, m2);
            m3 = fmaf(h3.x, w0, m3); m3 = fmaf(h3.y, w1, m3);
            m3 = fmaf(h3.z, w2, m3); m3 = fmaf(h3.w, w3, m3);
        }
        S[EO_MEAN + 0 * D + d] = m0;
        S[EO_MEAN + 1 * D + d] = m1;
        S[EO_MEAN + 2 * D + d] = m2;
        S[EO_MEAN + 3 * D + d] = m3;
    } else {
        int d = tid - D;
        float v0 = b_var[d], v1 = v0, v2 = v0, v3 = v0;
        #pragma unroll 2
        for (int k = 0; k < TWO_D; k += 4) {
            float4 h0 = *(float4*)&S[EO_H + 0 * TWO_D + k];
            float4 h1 = *(float4*)&S[EO_H + 1 * TWO_D + k];
            float4 h2 = *(float4*)&S[EO_H + 2 * TWO_D + k];
            float4 h3 = *(float4*)&S[EO_H + 3 * TWO_D + k];
            float w0 = W_var[(k + 0) * D + d];
            float w1 = W_var[(k + 1) * D + d];
            float w2 = W_var[(k + 2) * D + d];
            float w3 = W_var[(k + 3) * D + d];
            v0 = fmaf(h0.x, w0, v0); v0 = fmaf(h0.y, w1, v0);
            v0 = fmaf(h0.z, w2, v0); v0 = fmaf(h0.w, w3, v0);
            v1 = fmaf(h1.x, w0, v1); v1 = fmaf(h1.y, w1, v1);
            v1 = fmaf(h1.z, w2, v1); v1 = fmaf(h1.w, w3, v1);
            v2 = fmaf(h2.x, w0, v2); v2 = fmaf(h2.y, w1, v2);
            v2 = fmaf(h2.z, w2, v2); v2 = fmaf(h2.w, w3, v2);
            v3 = fmaf(h3.x, w0, v3); v3 = fmaf(h3.y, w1, v3);
            v3 = fmaf(h3.z, w2, v3); v3 = fmaf(h3.w, w3, v3);
        }
        S[EO_VAR + 0 * D + d] = softplus_f(v0);
        S[EO_VAR + 1 * D + d] = softplus_f(v1);
        S[EO_VAR + 2 * D + d] = softplus_f(v2);
        S[EO_VAR + 3 * D + d] = softplus_f(v3);
    }
    __syncthreads();

    // ---- z, KL ----
    float term[NB];
    #pragma unroll
    for (int nb = 0; nb < NB; nb++) term[nb] = 0.f;
    if (tid < D) {
        int d = tid;
        float eps = epsilon[d];
        #pragma unroll
        for (int nb = 0; nb < NB; nb++) {
            int b = b0 + nb;
            float m = S[EO_MEAN + nb * D + d];
            float v = S[EO_VAR + nb * D + d];
            float z = m + expf(0.5f * v) * eps;
            g_z[b * D + d] = z;
            float zn = __shfl_down_sync(0xffffffffu, z, 1);
            if (!(d & 1)) {
                __half2 hz = __floats2half2_rn(z, zn);
                g_zh2[(b * D + d) >> 1] = *(unsigned*)&hz;
            }
            float pm = prior_means[cid_s[nb] * D + d];
            float pv = softplus_f(prior_vars[cid_s[nb] * D + d]);
            float diff = pm - m;
            term[nb] = v / pv + diff * diff / pv - 1.f + logf(pv) - logf(v);
        }
    }
    #pragma unroll
    for (int nb = 0; nb < NB; nb++) {
        float t = term[nb];
        #pragma unroll
        for (int o = 16; o; o >>= 1) t += __shfl_xor_sync(0xffffffffu, t, o);
        if (tid < D && (tid & 31) == 0) red_s[nb][tid >> 5] = t;
    }
    __syncthreads();
    if (tid < NB) {
        float s = red_s[tid][0] + red_s[tid][1] + red_s[tid][2] + red_s[tid][3];
        g_kl[b0 + tid] = 0.5f * s;
    }
}

// ---------------- kernel 2: fp16 mma.sync vocab GEMM + fused softmax partials ----
__global__ void __launch_bounds__(256, 2) vocab_kernel(
    const float* __restrict__ Wv, const float* __restrict__ bvoc)
{
    __shared__ unsigned Ws[2 * WS_BUF];

    const int tid  = threadIdx.x;
    const int lane = tid & 31;
    const int w    = tid >> 5;
    const int g    = lane >> 2;
    const int cg   = lane & 3;
    const int v0   = blockIdx.x * N_CTA;
    const int b0   = blockIdx.y * M_CTA;

    const unsigned* zh0 = g_zh2 + (b0 + w * 16 + g) * (D / 2);
    const unsigned* zh1 = zh0 + 8 * (D / 2);

    const int n_f  = tid & 127;
    const int k2b  = tid >> 7;
    const int vf   = v0 + n_f;
    const bool okf = (vf < V);
    const float* wp = Wv + (okf ? vf : 0);

    float acc[16][4];
    #pragma unroll
    for (int t = 0; t < 16; t++)
        #pragma unroll
        for (int i = 0; i < 4; i++) acc[t][i] = 0.f;

    float plo[8], phi[8];
    #define LOADREGS(K0) do {                                                 \
        _Pragma("unroll")                                                     \
        for (int i = 0; i < 8; i++) {                                         \
            int kk = (K0) + 2 * (k2b + 2 * i);                                \
            plo[i] = okf ? wp[kk * V] : 0.f;                                  \
            phi[i] = okf ? wp[(kk + 1) * V] : 0.f;                            \
        } } while (0)
    #define STOREREGS(BUF) do {                                               \
        _Pragma("unroll")                                                     \
        for (int i = 0; i < 8; i++) {                                         \
            __half2 hv = __floats2half2_rn(plo[i], phi[i]);                   \
            (BUF)[(k2b + 2 * i) * WS_STRIDE + n_f] = *(unsigned*)&hv;         \
        } } while (0)

    LOADREGS(0);
    #pragma unroll
    for (int it = 0; it < 4; it++) {
        unsigned* buf = Ws + (it & 1) * WS_BUF;
        STOREREGS(buf);
        __syncthreads();
        if (it < 3) LOADREGS((it + 1) * KT);

        const int k0 = it * KT;
        #pragma unroll
        for (int ks = 0; ks < KT; ks += 16) {
            const int kh = (k0 + ks) >> 1;
            unsigned a0 = zh0[kh + cg];
            unsigned a1 = zh1[kh + cg];
            unsigned a2 = zh0[kh + cg + 4];
            unsigned a3 = zh1[kh + cg + 4];
            const unsigned* wsb0 = buf + ((ks >> 1) + cg) * WS_STRIDE + g;
            const unsigned* wsb1 = wsb0 + 4 * WS_STRIDE;
            #pragma unroll
            for (int t = 0; t < 16; t++)
                mma_f16(acc[t], a0, a1, a2, a3, wsb0[t * 8], wsb1[t * 8]);
        }
    }
    #undef LOADREGS
    #undef STOREREGS

    const int chunk = blockIdx.x;
    float m0 = -INFINITY, m1 = -INFINITY;
    #pragma unroll
    for (int t = 0; t < 16; t++) {
        int n = t * 8 + 2 * cg;
        bool ok0 = (v0 + n) < V;
        bool ok1 = (v0 + n + 1) < V;
        float bv0 = ok0 ? bvoc[v0 + n] : 0.f;
        float bv1 = ok1 ? bvoc[v0 + n + 1] : 0.f;
        acc[t][0] = ok0 ? acc[t][0] + bv0 : -INFINITY;
        acc[t][1] = ok1 ? acc[t][1] + bv1 : -INFINITY;
        acc[t][2] = ok0 ? acc[t][2] + bv0 : -INFINITY;
        acc[t][3] = ok1 ? acc[t][3] + bv1 : -INFINITY;
        m0 = fmaxf(m0, fmaxf(acc[t][0], acc[t][1]));
        m1 = fmaxf(m1, fmaxf(acc[t][2], acc[t][3]));
    }
    #pragma unroll
    for (int o = 1; o <= 2; o <<= 1) {
        m0 = fmaxf(m0, __shfl_xor_sync(0xffffffffu, m0, o));
        m1 = fmaxf(m1, __shfl_xor_sync(0xffffffffu, m1, o));
    }
    float s0 = 0.f, s1 = 0.f;
    #pragma unroll
    for (int t = 0; t < 16; t++) {
        s0 += __expf(acc[t][0] - m0) + __expf(acc[t][1] - m0);
        s1 += __expf(acc[t][2] - m1) + __expf(acc[t][3] - m1);
    }
    #pragma unroll
    for (int o = 1; o <= 2; o <<= 1) {
        s0 += __shfl_xor_sync(0xffffffffu, s0, o);
        s1 += __shfl_xor_sync(0xffffffffu, s1, o);
    }
    if (cg == 0) {
        int r0 = b0 + w * 16 + g;
        g_pmax[r0 * NCHUNK + chunk] = m0;
        g_psum[r0 * NCHUNK + chunk] = s0;
        g_pmax[(r0 + 8) * NCHUNK + chunk] = m1;
        g_psum[(r0 + 8) * NCHUNK + chunk] = s1;
    }
}

// ---------------- kernel 3: logsumexp combine + context gather + fused mean ----
__global__ void __launch_bounds__(128) finalize_rows(
    const float* __restrict__ Wv, const float* __restrict__ bvoc,
    const int* __restrict__ context_ids, float* __restrict__ out)
{
    __shared__ long long blk_s[4];

    const int warp = threadIdx.x >> 5;
    const int lane = threadIdx.x & 31;
    const int b = blockIdx.x * 4 + warp;

    float m = -INFINITY, s = 0.f;
    for (int ch = lane; ch < NCHUNK; ch += 32) {
        float m2 = g_pmax[b * NCHUNK + ch];
        float s2 = g_psum[b * NCHUNK + ch];
        if (m2 > m) { s = s * __expf(m - m2) + s2; m = m2; }
        else        { s += s2 * __expf(m2 - m); }
    }
    #pragma unroll
    for (int o = 16; o; o >>= 1) {
        float m2 = __shfl_xor_sync(0xffffffffu, m, o);
        float s2 = __shfl_xor_sync(0xffffffffu, s, o);
        if (m2 > m) { s = s * __expf(m - m2) + s2; m = m2; }
        else        { s += s2 * __expf(m2 - m); }
    }
    float lse = m + logf(s);

    float zr[4];
    #pragma unroll
    for (int t = 0; t < 4; t++) zr[t] = g_z[b * D + lane + 32 * t];

    float rec = 0.f;
    #pragma unroll
    for (int c = 0; c < C; c++) {
        int v = context_ids[b * C + c];
        float p = 0.f;
        #pragma unroll
        for (int t = 0; t < 4; t++)
            p = fmaf(zr[t], Wv[(lane + 32 * t) * V + v], p);
        #pragma unroll
        for (int o = 16; o; o >>= 1) p += __shfl_xor_sync(0xffffffffu, p, o);
        rec += p + bvoc[v] - lse;
    }

    if (lane == 0) {
        float val = rec - g_kl[b];
        blk_s[warp] = __double2ll_rn((double)val * 4294967296.0);
    }
    __syncthreads();
    if (threadIdx.x == 0) {
        long long bs = blk_s[0] + blk_s[1] + blk_s[2] + blk_s[3];
        atomicAdd((unsigned long long*)&g_acc, (unsigned long long)bs);
        __threadfence();
        unsigned int done = atomicAdd(&g_done, 1u);
        if (done == FIN_BLOCKS - 1) {
            long long tot = *(volatile long long*)&g_acc;
            out[0] = (float)((double)tot * (1.0 / 4294967296.0) * (1.0 / (double)B));
        }
    }
}

// ---------------- launch ----------------
extern "C" void kernel_launch(void* const* d_in, const int* in_sizes, int n_in,
                              void* d_out, int out_size)
{
    const int*   center_id   = (const int*)d_in[0];
    const int*   context_ids = (const int*)d_in[1];
    const float* epsilon     = (const float*)d_in[2];
    const float* emb         = (const float*)d_in[3];
    const float* prior_means = (const float*)d_in[4];
    const float* prior_vars  = (const float*)d_in[5];
    const float* W_enc       = (const float*)d_in[6];
    const float* b_enc       = (const float*)d_in[7];
    const float* W_mean      = (const float*)d_in[8];
    const float* b_mean      = (const float*)d_in[9];
    const float* W_var       = (const float*)d_in[10];
    const float* b_var       = (const float*)d_in[11];
    const float* W_vocab     = (const float*)d_in[12];
    const float* b_vocab     = (const float*)d_in[13];
    float* out = (float*)d_out;

    encoder_kernel<<<B / NB, 256>>>(center_id, context_ids, epsilon, emb,
                                    prior_means, prior_vars,
                                    W_enc, b_enc, W_mean, b_mean, W_var, b_var);

    dim3 grid2(NCHUNK, B / M_CTA);
    vocab_kernel<<<grid2, 256>>>(W_vocab, b_vocab);

    finalize_rows<<<FIN_BLOCKS, 128>>>(W_vocab, b_vocab, context_ids, out);
}

// round 16
// speedup vs baseline: 1.5055x; 1.5055x over previous
#include <cuda_runtime.h>
#include <cuda_fp16.h>
#include <cuda_bf16.h>
#include <math.h>
#include <stdint.h>

#define V 50257
#define D 128
#define B 1024
#define C 10
#define TWO_D 256
#define NB 4                 // batch rows per encoder CTA
#define NROW (NB * C)        // 40 cx rows per CTA

// vocab GEMM tiling (fp16 mma.sync m16n8k16)
#define M_CTA 128
#define N_CTA 128
#define KT 32
#define WS_STRIDE 136
#define WS_BUF (16 * WS_STRIDE)
#define NCHUNK ((V + N_CTA - 1) / N_CTA)   // 393
#define FIN_BLOCKS (B / 4)

// encoder smem layout (floats)
#define EO_A      0            // A_s   [40*128] = 5120
#define EO_CE     5120         // ce_s  [4*128]  = 512
#define EO_CP     5632         // cepart[4*256]  = 1024
#define EO_B      6656         // B_s   [16*256] = 4096 (main loop)  -> ends 10752
#define EO_HW     6656         // hw_s  [8*256]  = 2048 (post, aliases B)
#define EO_H      8704         // h_s   [4*256]  = 1024 (post, aliases B)
#define EO_MEAN   0            // mean_s[4*128]  = 512  (post, aliases A)
#define EO_VAR    512          // var_s [4*128]  = 512  (post, aliases A)
#define EO_TOTAL  10752

// ---------------- scratch ----------------
__device__ float              g_z[B * D];
__device__ unsigned           g_zh2[B * D / 2];
__device__ float              g_kl[B];
__device__ float              g_pmax[B * NCHUNK];
__device__ float              g_psum[B * NCHUNK];
__device__ long long          g_acc;
__device__ unsigned int       g_done;

__device__ __forceinline__ float softplus_fast(float x) {
    // max(x,0) + log1p(exp(-|x|)); fast-math variant, err ~1e-7 abs
    float e = __expf(-fabsf(x));
    return fmaxf(x, 0.f) + __logf(1.f + e);
}

__device__ __forceinline__ void mma_f16(float c[4],
                                        unsigned a0, unsigned a1, unsigned a2, unsigned a3,
                                        unsigned b0, unsigned b1) {
    asm volatile(
        "mma.sync.aligned.m16n8k16.row.col.f32.f16.f16.f32 "
        "{%0,%1,%2,%3}, {%4,%5,%6,%7}, {%8,%9}, {%0,%1,%2,%3};"
        : "+f"(c[0]), "+f"(c[1]), "+f"(c[2]), "+f"(c[3])
        : "r"(a0), "r"(a1), "r"(a2), "r"(a3), "r"(b0), "r"(b1));
}

// ---------------- kernel 1: register-tiled encoder + heads + KL + z ----------------
// cx GEMM [40,128]@[128,256]: 8 warps x 5 rows; thread = 5 rows x (4+4) cols.
__global__ void __launch_bounds__(256) encoder_kernel(
    const int* __restrict__ center_id, const int* __restrict__ context_ids,
    const float* __restrict__ epsilon, const float* __restrict__ emb,
    const float* __restrict__ prior_means, const float* __restrict__ prior_vars,
    const float* __restrict__ W_enc, const float* __restrict__ b_enc,
    const float* __restrict__ W_mean, const float* __restrict__ b_mean,
    const float* __restrict__ W_var, const float* __restrict__ b_var)
{
    __shared__ float S[EO_TOTAL];
    __shared__ int   ctx_s[NROW];
    __shared__ int   cid_s[NB];
    __shared__ float red_s[NB][4];

    const int b0   = blockIdx.x * NB;
    const int tid  = threadIdx.x;
    const int lane = tid & 31;
    const int w    = tid >> 5;
    const int l4   = lane * 4;

    if (blockIdx.x == 0 && tid == 0) { g_acc = 0ll; g_done = 0u; }

    if (tid < NB)   cid_s[tid] = center_id[b0 + tid];
    if (tid < NROW) ctx_s[tid] = context_ids[b0 * C + tid];
    __syncthreads();

    // gather ce (4x128) and A = cx (40x128), float4-coalesced
    if (tid < NB * 32) {
        int row = tid >> 5, l = tid & 31;
        *(float4*)&S[EO_CE + row * D + l * 4] =
            *(const float4*)&emb[cid_s[row] * D + l * 4];
    }
    for (int e = tid; e < NROW * 32; e += 256) {
        int row = e >> 5, l = e & 31;
        *(float4*)&S[EO_A + row * D + l * 4] =
            *(const float4*)&emb[ctx_s[row] * D + l * 4];
    }
    __syncthreads();

    // cepart[nb][j] = ce_nb . W1[:,j]  (j = tid); float4 reads + MLP-8 W loads
    {
        const int j = tid;
        float cp[NB] = {0.f, 0.f, 0.f, 0.f};
        #pragma unroll 2
        for (int k = 0; k < D; k += 4) {
            float4 c0 = *(float4*)&S[EO_CE + 0 * D + k];
            float4 c1 = *(float4*)&S[EO_CE + 1 * D + k];
            float4 c2 = *(float4*)&S[EO_CE + 2 * D + k];
            float4 c3 = *(float4*)&S[EO_CE + 3 * D + k];
            float w0 = W_enc[(k + 0) * TWO_D + j];
            float w1 = W_enc[(k + 1) * TWO_D + j];
            float w2 = W_enc[(k + 2) * TWO_D + j];
            float w3 = W_enc[(k + 3) * TWO_D + j];
            cp[0] = fmaf(c0.x, w0, cp[0]); cp[0] = fmaf(c0.y, w1, cp[0]);
            cp[0] = fmaf(c0.z, w2, cp[0]); cp[0] = fmaf(c0.w, w3, cp[0]);
            cp[1] = fmaf(c1.x, w0, cp[1]); cp[1] = fmaf(c1.y, w1, cp[1]);
            cp[1] = fmaf(c1.z, w2, cp[1]); cp[1] = fmaf(c1.w, w3, cp[1]);
            cp[2] = fmaf(c2.x, w0, cp[2]); cp[2] = fmaf(c2.y, w1, cp[2]);
            cp[2] = fmaf(c2.z, w2, cp[2]); cp[2] = fmaf(c2.w, w3, cp[2]);
            cp[3] = fmaf(c3.x, w0, cp[3]); cp[3] = fmaf(c3.y, w1, cp[3]);
            cp[3] = fmaf(c3.z, w2, cp[3]); cp[3] = fmaf(c3.w, w3, cp[3]);
        }
        #pragma unroll
        for (int nb = 0; nb < NB; nb++) S[EO_CP + nb * TWO_D + j] = cp[nb];
    }

    // ---- main cx GEMM, W2 staged in 16-k tiles, register prefetch ----
    float acc[5][8];
    #pragma unroll
    for (int i = 0; i < 5; i++)
        #pragma unroll
        for (int j = 0; j < 8; j++) acc[i][j] = 0.f;

    const float* W2 = W_enc + D * TWO_D;
    float4 pf[4];
    #pragma unroll
    for (int i = 0; i < 4; i++)
        pf[i] = *(const float4*)(W2 + tid * 4 + i * 1024);

    const int arow = w * 5 * D;
    #pragma unroll 1
    for (int kt = 0; kt < 8; kt++) {
        __syncthreads();                       // B_s readers from prev iter done
        #pragma unroll
        for (int i = 0; i < 4; i++)
            *(float4*)&S[EO_B + tid * 4 + i * 1024] = pf[i];
        __syncthreads();
        if (kt < 7) {
            #pragma unroll
            for (int i = 0; i < 4; i++)
                pf[i] = *(const float4*)(W2 + (kt + 1) * 4096 + tid * 4 + i * 1024);
        }
        const int kb = kt * 16;
        #pragma unroll
        for (int kk = 0; kk < 16; kk++) {
            float4 bv0 = *(float4*)&S[EO_B + kk * TWO_D + l4];
            float4 bv1 = *(float4*)&S[EO_B + kk * TWO_D + 128 + l4];
            #pragma unroll
            for (int i = 0; i < 5; i++) {
                float a = S[EO_A + arow + i * D + kb + kk];
                acc[i][0] = fmaf(a, bv0.x, acc[i][0]);
                acc[i][1] = fmaf(a, bv0.y, acc[i][1]);
                acc[i][2] = fmaf(a, bv0.z, acc[i][2]);
                acc[i][3] = fmaf(a, bv0.w, acc[i][3]);
                acc[i][4] = fmaf(a, bv1.x, acc[i][4]);
                acc[i][5] = fmaf(a, bv1.y, acc[i][5]);
                acc[i][6] = fmaf(a, bv1.z, acc[i][6]);
                acc[i][7] = fmaf(a, bv1.w, acc[i][7]);
            }
        }
    }
    __syncthreads();    // all B_s reads done before hw_s (aliased) writes

    // ---- epilogue: relu(acc + cepart + b_enc), sum over 5 rows -> warp partial ----
    {
        const int nb = w >> 1;
        float4 cp0 = *(float4*)&S[EO_CP + nb * TWO_D + l4];
        float4 cp1 = *(float4*)&S[EO_CP + nb * TWO_D + 128 + l4];
        float4 be0 = *(const float4*)&b_enc[l4];
        float4 be1 = *(const float4*)&b_enc[128 + l4];
        float hp[8];
        #pragma unroll
        for (int j = 0; j < 8; j++) hp[j] = 0.f;
        #pragma unroll
        for (int i = 0; i < 5; i++) {
            hp[0] += fmaxf(acc[i][0] + cp0.x + be0.x, 0.f);
            hp[1] += fmaxf(acc[i][1] + cp0.y + be0.y, 0.f);
            hp[2] += fmaxf(acc[i][2] + cp0.z + be0.z, 0.f);
            hp[3] += fmaxf(acc[i][3] + cp0.w + be0.w, 0.f);
            hp[4] += fmaxf(acc[i][4] + cp1.x + be1.x, 0.f);
            hp[5] += fmaxf(acc[i][5] + cp1.y + be1.y, 0.f);
            hp[6] += fmaxf(acc[i][6] + cp1.z + be1.z, 0.f);
            hp[7] += fmaxf(acc[i][7] + cp1.w + be1.w, 0.f);
        }
        *(float4*)&S[EO_HW + w * TWO_D + l4]       = make_float4(hp[0], hp[1], hp[2], hp[3]);
        *(float4*)&S[EO_HW + w * TWO_D + 128 + l4] = make_float4(hp[4], hp[5], hp[6], hp[7]);
    }
    __syncthreads();
    // combine warp pairs -> h[nb][j]
    for (int e = tid; e < NB * TWO_D; e += 256) {
        int nb = e >> 8, j = e & 255;
        S[EO_H + e] = S[EO_HW + (2 * nb) * TWO_D + j] + S[EO_HW + (2 * nb + 1) * TWO_D + j];
    }
    __syncthreads();

    // ---- heads: mean (threads 0..127), softplus(var) (threads 128..255) ----
    if (tid < D) {
        int d = tid;
        float m0 = b_mean[d], m1 = m0, m2 = m0, m3 = m0;
        #pragma unroll 2
        for (int k = 0; k < TWO_D; k += 4) {
            float4 h0 = *(float4*)&S[EO_H + 0 * TWO_D + k];
            float4 h1 = *(float4*)&S[EO_H + 1 * TWO_D + k];
            float4 h2 = *(float4*)&S[EO_H + 2 * TWO_D + k];
            float4 h3 = *(float4*)&S[EO_H + 3 * TWO_D + k];
            float w0 = W_mean[(k + 0) * D + d];
            float w1 = W_mean[(k + 1) * D + d];
            float w2 = W_mean[(k + 2) * D + d];
            float w3 = W_mean[(k + 3) * D + d];
            m0 = fmaf(h0.x, w0, m0); m0 = fmaf(h0.y, w1, m0);
            m0 = fmaf(h0.z, w2, m0); m0 = fmaf(h0.w, w3, m0);
            m1 = fmaf(h1.x, w0, m1); m1 = fmaf(h1.y, w1, m1);
            m1 = fmaf(h1.z, w2, m1); m1 = fmaf(h1.w, w3, m1);
            m2 = fmaf(h2.x, w0, m2); m2 = fmaf(h2.y, w1, m2);
            m2 = fmaf(h2.z, w2, m2); m2 = fmaf(h2.w, w3, m2);
            m3 = fmaf(h3.x, w0, m3); m3 = fmaf(h3.y, w1, m3);
            m3 = fmaf(h3.z, w2, m3); m3 = fmaf(h3.w, w3, m3);
        }
        S[EO_MEAN + 0 * D + d] = m0;
        S[EO_MEAN + 1 * D + d] = m1;
        S[EO_MEAN + 2 * D + d] = m2;
        S[EO_MEAN + 3 * D + d] = m3;
    } else {
        int d = tid - D;
        float v0 = b_var[d], v1 = v0, v2 = v0, v3 = v0;
        #pragma unroll 2
        for (int k = 0; k < TWO_D; k += 4) {
            float4 h0 = *(float4*)&S[EO_H + 0 * TWO_D + k];
            float4 h1 = *(float4*)&S[EO_H + 1 * TWO_D + k];
            float4 h2 = *(float4*)&S[EO_H + 2 * TWO_D + k];
            float4 h3 = *(float4*)&S[EO_H + 3 * TWO_D + k];
            float w0 = W_var[(k + 0) * D + d];
            float w1 = W_var[(k + 1) * D + d];
            float w2 = W_var[(k + 2) * D + d];
            float w3 = W_var[(k + 3) * D + d];
            v0 = fmaf(h0.x, w0, v0); v0 = fmaf(h0.y, w1, v0);
            v0 = fmaf(h0.z, w2, v0); v0 = fmaf(h0.w, w3, v0);
            v1 = fmaf(h1.x, w0, v1); v1 = fmaf(h1.y, w1, v1);
            v1 = fmaf(h1.z, w2, v1); v1 = fmaf(h1.w, w3, v1);
            v2 = fmaf(h2.x, w0, v2); v2 = fmaf(h2.y, w1, v2);
            v2 = fmaf(h2.z, w2, v2); v2 = fmaf(h2.w, w3, v2);
            v3 = fmaf(h3.x, w0, v3); v3 = fmaf(h3.y, w1, v3);
            v3 = fmaf(h3.z, w2, v3); v3 = fmaf(h3.w, w3, v3);
        }
        S[EO_VAR + 0 * D + d] = softplus_fast(v0);
        S[EO_VAR + 1 * D + d] = softplus_fast(v1);
        S[EO_VAR + 2 * D + d] = softplus_fast(v2);
        S[EO_VAR + 3 * D + d] = softplus_fast(v3);
    }
    __syncthreads();

    // ---- z, KL (fast-math transcendentals; err << 1e-3 threshold) ----
    float term[NB];
    #pragma unroll
    for (int nb = 0; nb < NB; nb++) term[nb] = 0.f;
    if (tid < D) {
        int d = tid;
        float eps = epsilon[d];
        #pragma unroll
        for (int nb = 0; nb < NB; nb++) {
            int b = b0 + nb;
            float m = S[EO_MEAN + nb * D + d];
            float v = S[EO_VAR + nb * D + d];
            float z = m + __expf(0.5f * v) * eps;
            g_z[b * D + d] = z;
            float zn = __shfl_down_sync(0xffffffffu, z, 1);
            if (!(d & 1)) {
                __half2 hz = __floats2half2_rn(z, zn);
                g_zh2[(b * D + d) >> 1] = *(unsigned*)&hz;
            }
            float pm = prior_means[cid_s[nb] * D + d];
            float pv = softplus_fast(prior_vars[cid_s[nb] * D + d]);
            float diff = pm - m;
            term[nb] = v / pv + diff * diff / pv - 1.f + __logf(pv) - __logf(v);
        }
    }
    #pragma unroll
    for (int nb = 0; nb < NB; nb++) {
        float t = term[nb];
        #pragma unroll
        for (int o = 16; o; o >>= 1) t += __shfl_xor_sync(0xffffffffu, t, o);
        if (tid < D && (tid & 31) == 0) red_s[nb][tid >> 5] = t;
    }
    __syncthreads();
    if (tid < NB) {
        float s = red_s[tid][0] + red_s[tid][1] + red_s[tid][2] + red_s[tid][3];
        g_kl[b0 + tid] = 0.5f * s;
    }
}

// ---------------- kernel 2: fp16 mma.sync vocab GEMM + fused softmax partials ----
__global__ void __launch_bounds__(256, 2) vocab_kernel(
    const float* __restrict__ Wv, const float* __restrict__ bvoc)
{
    __shared__ unsigned Ws[2 * WS_BUF];

    const int tid  = threadIdx.x;
    const int lane = tid & 31;
    const int w    = tid >> 5;
    const int g    = lane >> 2;
    const int cg   = lane & 3;
    const int v0   = blockIdx.x * N_CTA;
    const int b0   = blockIdx.y * M_CTA;

    const unsigned* zh0 = g_zh2 + (b0 + w * 16 + g) * (D / 2);
    const unsigned* zh1 = zh0 + 8 * (D / 2);

    const int n_f  = tid & 127;
    const int k2b  = tid >> 7;
    const int vf   = v0 + n_f;
    const bool okf = (vf < V);
    const float* wp = Wv + (okf ? vf : 0);

    float acc[16][4];
    #pragma unroll
    for (int t = 0; t < 16; t++)
        #pragma unroll
        for (int i = 0; i < 4; i++) acc[t][i] = 0.f;

    float plo[8], phi[8];
    #define LOADREGS(K0) do {                                                 \
        _Pragma("unroll")                                                     \
        for (int i = 0; i < 8; i++) {                                         \
            int kk = (K0) + 2 * (k2b + 2 * i);                                \
            plo[i] = okf ? wp[kk * V] : 0.f;                                  \
            phi[i] = okf ? wp[(kk + 1) * V] : 0.f;                            \
        } } while (0)
    #define STOREREGS(BUF) do {                                               \
        _Pragma("unroll")                                                     \
        for (int i = 0; i < 8; i++) {                                         \
            __half2 hv = __floats2half2_rn(plo[i], phi[i]);                   \
            (BUF)[(k2b + 2 * i) * WS_STRIDE + n_f] = *(unsigned*)&hv;         \
        } } while (0)

    LOADREGS(0);
    #pragma unroll
    for (int it = 0; it < 4; it++) {
        unsigned* buf = Ws + (it & 1) * WS_BUF;
        STOREREGS(buf);
        __syncthreads();
        if (it < 3) LOADREGS((it + 1) * KT);

        const int k0 = it * KT;
        #pragma unroll
        for (int ks = 0; ks < KT; ks += 16) {
            const int kh = (k0 + ks) >> 1;
            unsigned a0 = zh0[kh + cg];
            unsigned a1 = zh1[kh + cg];
            unsigned a2 = zh0[kh + cg + 4];
            unsigned a3 = zh1[kh + cg + 4];
            const unsigned* wsb0 = buf + ((ks >> 1) + cg) * WS_STRIDE + g;
            const unsigned* wsb1 = wsb0 + 4 * WS_STRIDE;
            #pragma unroll
            for (int t = 0; t < 16; t++)
                mma_f16(acc[t], a0, a1, a2, a3, wsb0[t * 8], wsb1[t * 8]);
        }
    }
    #undef LOADREGS
    #undef STOREREGS

    const int chunk = blockIdx.x;
    float m0 = -INFINITY, m1 = -INFINITY;
    #pragma unroll
    for (int t = 0; t < 16; t++) {
        int n = t * 8 + 2 * cg;
        bool ok0 = (v0 + n) < V;
        bool ok1 = (v0 + n + 1) < V;
        float bv0 = ok0 ? bvoc[v0 + n] : 0.f;
        float bv1 = ok1 ? bvoc[v0 + n + 1] : 0.f;
        acc[t][0] = ok0 ? acc[t][0] + bv0 : -INFINITY;
        acc[t][1] = ok1 ? acc[t][1] + bv1 : -INFINITY;
        acc[t][2] = ok0 ? acc[t][2] + bv0 : -INFINITY;
        acc[t][3] = ok1 ? acc[t][3] + bv1 : -INFINITY;
        m0 = fmaxf(m0, fmaxf(acc[t][0], acc[t][1]));
        m1 = fmaxf(m1, fmaxf(acc[t][2], acc[t][3]));
    }
    #pragma unroll
    for (int o = 1; o <= 2; o <<= 1) {
        m0 = fmaxf(m0, __shfl_xor_sync(0xffffffffu, m0, o));
        m1 = fmaxf(m1, __shfl_xor_sync(0xffffffffu, m1, o));
    }
    float s0 = 0.f, s1 = 0.f;
    #pragma unroll
    for (int t = 0; t < 16; t++) {
        s0 += __expf(acc[t][0] - m0) + __expf(acc[t][1] - m0);
        s1 += __expf(acc[t][2] - m1) + __expf(acc[t][3] - m1);
    }
    #pragma unroll
    for (int o = 1; o <= 2; o <<= 1) {
        s0 += __shfl_xor_sync(0xffffffffu, s0, o);
        s1 += __shfl_xor_sync(0xffffffffu, s1, o);
    }
    if (cg == 0) {
        int r0 = b0 + w * 16 + g;
        g_pmax[r0 * NCHUNK + chunk] = m0;
        g_psum[r0 * NCHUNK + chunk] = s0;
        g_pmax[(r0 + 8) * NCHUNK + chunk] = m1;
        g_psum[(r0 + 8) * NCHUNK + chunk] = s1;
    }
}

// ---------------- kernel 3: logsumexp combine + context gather + fused mean ----
__global__ void __launch_bounds__(128) finalize_rows(
    const float* __restrict__ Wv, const float* __restrict__ bvoc,
    const int* __restrict__ context_ids, float* __restrict__ out)
{
    __shared__ long long blk_s[4];

    const int warp = threadIdx.x >> 5;
    const int lane = threadIdx.x & 31;
    const int b = blockIdx.x * 4 + warp;

    float m = -INFINITY, s = 0.f;
    for (int ch = lane; ch < NCHUNK; ch += 32) {
        float m2 = g_pmax[b * NCHUNK + ch];
        float s2 = g_psum[b * NCHUNK + ch];
        if (m2 > m) { s = s * __expf(m - m2) + s2; m = m2; }
        else        { s += s2 * __expf(m2 - m); }
    }
    #pragma unroll
    for (int o = 16; o; o >>= 1) {
        float m2 = __shfl_xor_sync(0xffffffffu, m, o);
        float s2 = __shfl_xor_sync(0xffffffffu, s, o);
        if (m2 > m) { s = s * __expf(m - m2) + s2; m = m2; }
        else        { s += s2 * __expf(m2 - m); }
    }
    float lse = m + logf(s);

    float zr[4];
    #pragma unroll
    for (int t = 0; t < 4; t++) zr[t] = g_z[b * D + lane + 32 * t];

    float rec = 0.f;
    #pragma unroll
    for (int c = 0; c < C; c++) {
        int v = context_ids[b * C + c];
        float p = 0.f;
        #pragma unroll
        for (int t = 0; t < 4; t++)
            p = fmaf(zr[t], Wv[(lane + 32 * t) * V + v], p);
        #pragma unroll
        for (int o = 16; o; o >>= 1) p += __shfl_xor_sync(0xffffffffu, p, o);
        rec += p + bvoc[v] - lse;
    }

    if (lane == 0) {
        float val = rec - g_kl[b];
        blk_s[warp] = __double2ll_rn((double)val * 4294967296.0);
    }
    __syncthreads();
    if (threadIdx.x == 0) {
        long long bs = blk_s[0] + blk_s[1] + blk_s[2] + blk_s[3];
        atomicAdd((unsigned long long*)&g_acc, (unsigned long long)bs);
        __threadfence();
        unsigned int done = atomicAdd(&g_done, 1u);
        if (done == FIN_BLOCKS - 1) {
            long long tot = *(volatile long long*)&g_acc;
            out[0] = (float)((double)tot * (1.0 / 4294967296.0) * (1.0 / (double)B));
        }
    }
}

// ---------------- launch ----------------
extern "C" void kernel_launch(void* const* d_in, const int* in_sizes, int n_in,
                              void* d_out, int out_size)
{
    const int*   center_id   = (const int*)d_in[0];
    const int*   context_ids = (const int*)d_in[1];
    const float* epsilon     = (const float*)d_in[2];
    const float* emb         = (const float*)d_in[3];
    const float* prior_means = (const float*)d_in[4];
    const float* prior_vars  = (const float*)d_in[5];
    const float* W_enc       = (const float*)d_in[6];
    const float* b_enc       = (const float*)d_in[7];
    const float* W_mean      = (const float*)d_in[8];
    const float* b_mean      = (const float*)d_in[9];
    const float* W_var       = (const float*)d_in[10];
    const float* b_var       = (const float*)d_in[11];
    const float* W_vocab     = (const float*)d_in[12];
    const float* b_vocab     = (const float*)d_in[13];
    float* out = (float*)d_out;

    encoder_kernel<<<B / NB, 256>>>(center_id, context_ids, epsilon, emb,
                                    prior_means, prior_vars,
                                    W_enc, b_enc, W_mean, b_mean, W_var, b_var);

    dim3 grid2(NCHUNK, B / M_CTA);
    vocab_kernel<<<grid2, 256>>>(W_vocab, b_vocab);

    finalize_rows<<<FIN_BLOCKS, 128>>>(W_vocab, b_vocab, context_ids, out);
}

// round 17
// speedup vs baseline: 1.5368x; 1.0208x over previous
#include <cuda_runtime.h>
#include <cuda_fp16.h>
#include <cuda_bf16.h>
#include <math.h>
#include <stdint.h>

#define V 50257
#define D 128
#define B 1024
#define C 10
#define TWO_D 256
#define NB 4                 // batch rows per encoder CTA
#define NROW (NB * C)        // 40 real encoder rows per CTA

// vocab GEMM tiling (fp16 mma.sync m16n8k16)
#define M_CTA 128
#define N_CTA 128
#define KT 32
#define WS_STRIDE 136
#define WS_BUF (16 * WS_STRIDE)
#define NCHUNK ((V + N_CTA - 1) / N_CTA)   // 393
#define FIN_BLOCKS (B / 4)

// encoder (tensor-core) smem layout, dynamic, byte offsets
#define AST 132                      // A row stride in u32 (half2); 132%32=4 -> conflict-free
#define BST 264                      // B k2-row stride in u32;     264%32=8 -> conflict-free
#define OA  0                        // A: 64 rows x 132 u32 = 33792 B
#define OB  33792                    // B stage: 16 x 264 u32 = 16896 B
#define OH  50688                    // h[4][256] f32 = 4096 B
#define OMV 54784                    // mean[4][128] + var[4][128] f32 = 4096 B
#define ESMEM 58880

// ---------------- scratch ----------------
__device__ float              g_z[B * D];
__device__ unsigned           g_zh2[B * D / 2];
__device__ float              g_kl[B];
__device__ float              g_pmax[B * NCHUNK];
__device__ float              g_psum[B * NCHUNK];
__device__ long long          g_acc;
__device__ unsigned int       g_done;

__device__ __forceinline__ float softplus_fast(float x) {
    float e = __expf(-fabsf(x));
    return fmaxf(x, 0.f) + __logf(1.f + e);
}

__device__ __forceinline__ void mma_f16(float c[4],
                                        unsigned a0, unsigned a1, unsigned a2, unsigned a3,
                                        unsigned b0, unsigned b1) {
    asm volatile(
        "mma.sync.aligned.m16n8k16.row.col.f32.f16.f16.f32 "
        "{%0,%1,%2,%3}, {%4,%5,%6,%7}, {%8,%9}, {%0,%1,%2,%3};"
        : "+f"(c[0]), "+f"(c[1]), "+f"(c[2]), "+f"(c[3])
        : "r"(a0), "r"(a1), "r"(a2), "r"(a3), "r"(b0), "r"(b1));
}

// ---------------- kernel 1: tensor-core encoder + heads + KL + z ----------------
// Single GEMM [64(=4nb x16 rows, 40 real), K=256(concat ce|cx), N=256] in fp16 mma.
// 8 warps = 4 nb-tiles x 2 n-halves; warp's rows all belong to ONE nb.
__global__ void __launch_bounds__(256, 2) encoder_kernel(
    const int* __restrict__ center_id, const int* __restrict__ context_ids,
    const float* __restrict__ epsilon, const float* __restrict__ emb,
    const float* __restrict__ prior_means, const float* __restrict__ prior_vars,
    const float* __restrict__ W_enc, const float* __restrict__ b_enc,
    const float* __restrict__ W_mean, const float* __restrict__ b_mean,
    const float* __restrict__ W_var, const float* __restrict__ b_var)
{
    extern __shared__ char ES[];
    unsigned* HA = (unsigned*)(ES + OA);
    unsigned* HB = (unsigned*)(ES + OB);
    float*    Hs = (float*)(ES + OH);     // h[4][256]
    float*    MV = (float*)(ES + OMV);    // mean[4][128] | var[4][128]

    __shared__ int   ctx_s[NROW];
    __shared__ int   cid_s[NB];
    __shared__ float red_s[NB][4];

    const int b0   = blockIdx.x * NB;
    const int tid  = threadIdx.x;
    const int lane = tid & 31;
    const int w    = tid >> 5;
    const int mw   = w >> 1;      // nb tile 0..3
    const int nh   = w & 1;       // n half
    const int g    = lane >> 2;
    const int cg   = lane & 3;

    if (blockIdx.x == 0 && tid == 0) { g_acc = 0ll; g_done = 0u; }

    if (tid < NB)   cid_s[tid] = center_id[b0 + tid];
    if (tid < NROW) ctx_s[tid] = context_ids[b0 * C + tid];
    __syncthreads();

    // zero pad rows (c = 10..15 per nb): 24 rows x 128 half2
    for (int e = tid; e < 24 * 128; e += 256) {
        int pr = e >> 7, q = e & 127;
        int nb = pr / 6, c = 10 + pr % 6;
        HA[(nb * 16 + c) * AST + q] = 0u;
    }
    // fill real rows: row (nb*16+c), k2 q: q<64 -> ce_nb halves, q>=64 -> cx halves
    for (int e = tid; e < NROW * 128; e += 256) {
        int lr = e >> 7, q = e & 127;
        int nb = lr / 10, c = lr % 10;
        int r = nb * 16 + c;
        const float* src = (q < 64) ? (emb + cid_s[nb] * D + 2 * q)
                                    : (emb + ctx_s[lr] * D + 2 * (q - 64));
        float2 f2 = *(const float2*)src;
        __half2 hv = __floats2half2_rn(f2.x, f2.y);
        HA[r * AST + q] = *(unsigned*)&hv;
    }

    float acc[16][4];
    #pragma unroll
    for (int t = 0; t < 16; t++)
        #pragma unroll
        for (int i = 0; i < 4; i++) acc[t][i] = 0.f;

    const int r0 = mw * 16 + g;
    const int bcolg = nh * 128 + g;

    #pragma unroll 1
    for (int kt = 0; kt < 8; kt++) {
        __syncthreads();
        // stage W_enc k2 in [kt*16, kt*16+16): 16 x 256 half2, coalesced in n
        #pragma unroll
        for (int i = 0; i < 16; i++) {
            int kk2 = i;                     // e = tid + 256*i -> kk2 = i, n = tid
            int k = (kt * 16 + kk2) * 2;
            __half2 hv = __floats2half2_rn(W_enc[k * TWO_D + tid],
                                           W_enc[(k + 1) * TWO_D + tid]);
            HB[kk2 * BST + tid] = *(unsigned*)&hv;
        }
        __syncthreads();
        #pragma unroll
        for (int ks2 = 0; ks2 < 16; ks2 += 8) {
            int kh = kt * 16 + ks2;
            unsigned a0 = HA[r0 * AST + kh + cg];
            unsigned a1 = HA[(r0 + 8) * AST + kh + cg];
            unsigned a2 = HA[r0 * AST + kh + cg + 4];
            unsigned a3 = HA[(r0 + 8) * AST + kh + cg + 4];
            const unsigned* wsb0 = HB + (ks2 + cg) * BST + bcolg;
            const unsigned* wsb1 = wsb0 + 4 * BST;
            #pragma unroll
            for (int t = 0; t < 16; t++)
                mma_f16(acc[t], a0, a1, a2, a3, wsb0[t * 8], wsb1[t * 8]);
        }
    }
    __syncthreads();

    // epilogue: h[nb][col] = sum_c relu(acc + b_enc[col]); rows r0 (c=g, always
    // real) and r1 (c=g+8, real iff g<2); reduce over g via shfl.
    {
        const bool r1ok = (g < 2);
        #pragma unroll
        for (int t = 0; t < 16; t++) {
            int col = nh * 128 + t * 8 + 2 * cg;
            float be0 = b_enc[col], be1 = b_enc[col + 1];
            float h0 = fmaxf(acc[t][0] + be0, 0.f);
            float h1 = fmaxf(acc[t][1] + be1, 0.f);
            if (r1ok) {
                h0 += fmaxf(acc[t][2] + be0, 0.f);
                h1 += fmaxf(acc[t][3] + be1, 0.f);
            }
            #pragma unroll
            for (int o = 4; o <= 16; o <<= 1) {
                h0 += __shfl_xor_sync(0xffffffffu, h0, o);
                h1 += __shfl_xor_sync(0xffffffffu, h1, o);
            }
            if (g == 0) {
                Hs[mw * TWO_D + col]     = h0;
                Hs[mw * TWO_D + col + 1] = h1;
            }
        }
    }
    __syncthreads();

    // ---- heads: mean (threads 0..127), softplus(var) (threads 128..255), fp32 ----
    if (tid < D) {
        int d = tid;
        float m0 = b_mean[d], m1 = m0, m2 = m0, m3 = m0;
        #pragma unroll 2
        for (int k = 0; k < TWO_D; k += 4) {
            float4 h0 = *(float4*)&Hs[0 * TWO_D + k];
            float4 h1 = *(float4*)&Hs[1 * TWO_D + k];
            float4 h2 = *(float4*)&Hs[2 * TWO_D + k];
            float4 h3 = *(float4*)&Hs[3 * TWO_D + k];
            float w0 = W_mean[(k + 0) * D + d];
            float w1 = W_mean[(k + 1) * D + d];
            float w2 = W_mean[(k + 2) * D + d];
            float w3 = W_mean[(k + 3) * D + d];
            m0 = fmaf(h0.x, w0, m0); m0 = fmaf(h0.y, w1, m0);
            m0 = fmaf(h0.z, w2, m0); m0 = fmaf(h0.w, w3, m0);
            m1 = fmaf(h1.x, w0, m1); m1 = fmaf(h1.y, w1, m1);
            m1 = fmaf(h1.z, w2, m1); m1 = fmaf(h1.w, w3, m1);
            m2 = fmaf(h2.x, w0, m2); m2 = fmaf(h2.y, w1, m2);
            m2 = fmaf(h2.z, w2, m2); m2 = fmaf(h2.w, w3, m2);
            m3 = fmaf(h3.x, w0, m3); m3 = fmaf(h3.y, w1, m3);
            m3 = fmaf(h3.z, w2, m3); m3 = fmaf(h3.w, w3, m3);
        }
        MV[0 * D + d] = m0; MV[1 * D + d] = m1;
        MV[2 * D + d] = m2; MV[3 * D + d] = m3;
    } else {
        int d = tid - D;
        float v0 = b_var[d], v1 = v0, v2 = v0, v3 = v0;
        #pragma unroll 2
        for (int k = 0; k < TWO_D; k += 4) {
            float4 h0 = *(float4*)&Hs[0 * TWO_D + k];
            float4 h1 = *(float4*)&Hs[1 * TWO_D + k];
            float4 h2 = *(float4*)&Hs[2 * TWO_D + k];
            float4 h3 = *(float4*)&Hs[3 * TWO_D + k];
            float w0 = W_var[(k + 0) * D + d];
            float w1 = W_var[(k + 1) * D + d];
            float w2 = W_var[(k + 2) * D + d];
            float w3 = W_var[(k + 3) * D + d];
            v0 = fmaf(h0.x, w0, v0); v0 = fmaf(h0.y, w1, v0);
            v0 = fmaf(h0.z, w2, v0); v0 = fmaf(h0.w, w3, v0);
            v1 = fmaf(h1.x, w0, v1); v1 = fmaf(h1.y, w1, v1);
            v1 = fmaf(h1.z, w2, v1); v1 = fmaf(h1.w, w3, v1);
            v2 = fmaf(h2.x, w0, v2); v2 = fmaf(h2.y, w1, v2);
            v2 = fmaf(h2.z, w2, v2); v2 = fmaf(h2.w, w3, v2);
            v3 = fmaf(h3.x, w0, v3); v3 = fmaf(h3.y, w1, v3);
            v3 = fmaf(h3.z, w2, v3); v3 = fmaf(h3.w, w3, v3);
        }
        MV[512 + 0 * D + d] = softplus_fast(v0);
        MV[512 + 1 * D + d] = softplus_fast(v1);
        MV[512 + 2 * D + d] = softplus_fast(v2);
        MV[512 + 3 * D + d] = softplus_fast(v3);
    }
    __syncthreads();

    // ---- z, KL (fp32, fast-math transcendentals) ----
    float term[NB];
    #pragma unroll
    for (int nb = 0; nb < NB; nb++) term[nb] = 0.f;
    if (tid < D) {
        int d = tid;
        float eps = epsilon[d];
        #pragma unroll
        for (int nb = 0; nb < NB; nb++) {
            int b = b0 + nb;
            float m = MV[nb * D + d];
            float v = MV[512 + nb * D + d];
            float z = m + __expf(0.5f * v) * eps;
            g_z[b * D + d] = z;
            float zn = __shfl_down_sync(0xffffffffu, z, 1);
            if (!(d & 1)) {
                __half2 hz = __floats2half2_rn(z, zn);
                g_zh2[(b * D + d) >> 1] = *(unsigned*)&hz;
            }
            float pm = prior_means[cid_s[nb] * D + d];
            float pv = softplus_fast(prior_vars[cid_s[nb] * D + d]);
            float diff = pm - m;
            term[nb] = v / pv + diff * diff / pv - 1.f + __logf(pv) - __logf(v);
        }
    }
    #pragma unroll
    for (int nb = 0; nb < NB; nb++) {
        float t = term[nb];
        #pragma unroll
        for (int o = 16; o; o >>= 1) t += __shfl_xor_sync(0xffffffffu, t, o);
        if (tid < D && (tid & 31) == 0) red_s[nb][tid >> 5] = t;
    }
    __syncthreads();
    if (tid < NB) {
        float s = red_s[tid][0] + red_s[tid][1] + red_s[tid][2] + red_s[tid][3];
        g_kl[b0 + tid] = 0.5f * s;
    }
}

// ---------------- kernel 2: fp16 mma.sync vocab GEMM + fused softmax partials ----
__global__ void __launch_bounds__(256, 2) vocab_kernel(
    const float* __restrict__ Wv, const float* __restrict__ bvoc)
{
    __shared__ unsigned Ws[2 * WS_BUF];

    const int tid  = threadIdx.x;
    const int lane = tid & 31;
    const int w    = tid >> 5;
    const int g    = lane >> 2;
    const int cg   = lane & 3;
    const int v0   = blockIdx.x * N_CTA;
    const int b0   = blockIdx.y * M_CTA;

    const unsigned* zh0 = g_zh2 + (b0 + w * 16 + g) * (D / 2);
    const unsigned* zh1 = zh0 + 8 * (D / 2);

    const int n_f  = tid & 127;
    const int k2b  = tid >> 7;
    const int vf   = v0 + n_f;
    const bool okf = (vf < V);
    const float* wp = Wv + (okf ? vf : 0);

    float acc[16][4];
    #pragma unroll
    for (int t = 0; t < 16; t++)
        #pragma unroll
        for (int i = 0; i < 4; i++) acc[t][i] = 0.f;

    float plo[8], phi[8];
    #define LOADREGS(K0) do {                                                 \
        _Pragma("unroll")                                                     \
        for (int i = 0; i < 8; i++) {                                         \
            int kk = (K0) + 2 * (k2b + 2 * i);                                \
            plo[i] = okf ? wp[kk * V] : 0.f;                                  \
            phi[i] = okf ? wp[(kk + 1) * V] : 0.f;                            \
        } } while (0)
    #define STOREREGS(BUF) do {                                               \
        _Pragma("unroll")                                                     \
        for (int i = 0; i < 8; i++) {                                         \
            __half2 hv = __floats2half2_rn(plo[i], phi[i]);                   \
            (BUF)[(k2b + 2 * i) * WS_STRIDE + n_f] = *(unsigned*)&hv;         \
        } } while (0)

    LOADREGS(0);
    #pragma unroll
    for (int it = 0; it < 4; it++) {
        unsigned* buf = Ws + (it & 1) * WS_BUF;
        STOREREGS(buf);
        __syncthreads();
        if (it < 3) LOADREGS((it + 1) * KT);

        const int k0 = it * KT;
        #pragma unroll
        for (int ks = 0; ks < KT; ks += 16) {
            const int kh = (k0 + ks) >> 1;
            unsigned a0 = zh0[kh + cg];
            unsigned a1 = zh1[kh + cg];
            unsigned a2 = zh0[kh + cg + 4];
            unsigned a3 = zh1[kh + cg + 4];
            const unsigned* wsb0 = buf + ((ks >> 1) + cg) * WS_STRIDE + g;
            const unsigned* wsb1 = wsb0 + 4 * WS_STRIDE;
            #pragma unroll
            for (int t = 0; t < 16; t++)
                mma_f16(acc[t], a0, a1, a2, a3, wsb0[t * 8], wsb1[t * 8]);
        }
    }
    #undef LOADREGS
    #undef STOREREGS

    const int chunk = blockIdx.x;
    float m0 = -INFINITY, m1 = -INFINITY;
    #pragma unroll
    for (int t = 0; t < 16; t++) {
        int n = t * 8 + 2 * cg;
        bool ok0 = (v0 + n) < V;
        bool ok1 = (v0 + n + 1) < V;
        float bv0 = ok0 ? bvoc[v0 + n] : 0.f;
        float bv1 = ok1 ? bvoc[v0 + n + 1] : 0.f;
        acc[t][0] = ok0 ? acc[t][0] + bv0 : -INFINITY;
        acc[t][1] = ok1 ? acc[t][1] + bv1 : -INFINITY;
        acc[t][2] = ok0 ? acc[t][2] + bv0 : -INFINITY;
        acc[t][3] = ok1 ? acc[t][3] + bv1 : -INFINITY;
        m0 = fmaxf(m0, fmaxf(acc[t][0], acc[t][1]));
        m1 = fmaxf(m1, fmaxf(acc[t][2], acc[t][3]));
    }
    #pragma unroll
    for (int o = 1; o <= 2; o <<= 1) {
        m0 = fmaxf(m0, __shfl_xor_sync(0xffffffffu, m0, o));
        m1 = fmaxf(m1, __shfl_xor_sync(0xffffffffu, m1, o));
    }
    float s0 = 0.f, s1 = 0.f;
    #pragma unroll
    for (int t = 0; t < 16; t++) {
        s0 += __expf(acc[t][0] - m0) + __expf(acc[t][1] - m0);
        s1 += __expf(acc[t][2] - m1) + __expf(acc[t][3] - m1);
    }
    #pragma unroll
    for (int o = 1; o <= 2; o <<= 1) {
        s0 += __shfl_xor_sync(0xffffffffu, s0, o);
        s1 += __shfl_xor_sync(0xffffffffu, s1, o);
    }
    if (cg == 0) {
        int r0 = b0 + w * 16 + g;
        g_pmax[r0 * NCHUNK + chunk] = m0;
        g_psum[r0 * NCHUNK + chunk] = s0;
        g_pmax[(r0 + 8) * NCHUNK + chunk] = m1;
        g_psum[(r0 + 8) * NCHUNK + chunk] = s1;
    }
}

// ---------------- kernel 3: logsumexp combine + context gather + fused mean ----
__global__ void __launch_bounds__(128) finalize_rows(
    const float* __restrict__ Wv, const float* __restrict__ bvoc,
    const int* __restrict__ context_ids, float* __restrict__ out)
{
    __shared__ long long blk_s[4];

    const int warp = threadIdx.x >> 5;
    const int lane = threadIdx.x & 31;
    const int b = blockIdx.x * 4 + warp;

    float m = -INFINITY, s = 0.f;
    for (int ch = lane; ch < NCHUNK; ch += 32) {
        float m2 = g_pmax[b * NCHUNK + ch];
        float s2 = g_psum[b * NCHUNK + ch];
        if (m2 > m) { s = s * __expf(m - m2) + s2; m = m2; }
        else        { s += s2 * __expf(m2 - m); }
    }
    #pragma unroll
    for (int o = 16; o; o >>= 1) {
        float m2 = __shfl_xor_sync(0xffffffffu, m, o);
        float s2 = __shfl_xor_sync(0xffffffffu, s, o);
        if (m2 > m) { s = s * __expf(m - m2) + s2; m = m2; }
        else        { s += s2 * __expf(m2 - m); }
    }
    float lse = m + logf(s);

    float zr[4];
    #pragma unroll
    for (int t = 0; t < 4; t++) zr[t] = g_z[b * D + lane + 32 * t];

    float rec = 0.f;
    #pragma unroll
    for (int c = 0; c < C; c++) {
        int v = context_ids[b * C + c];
        float p = 0.f;
        #pragma unroll
        for (int t = 0; t < 4; t++)
            p = fmaf(zr[t], Wv[(lane + 32 * t) * V + v], p);
        #pragma unroll
        for (int o = 16; o; o >>= 1) p += __shfl_xor_sync(0xffffffffu, p, o);
        rec += p + bvoc[v] - lse;
    }

    if (lane == 0) {
        float val = rec - g_kl[b];
        blk_s[warp] = __double2ll_rn((double)val * 4294967296.0);
    }
    __syncthreads();
    if (threadIdx.x == 0) {
        long long bs = blk_s[0] + blk_s[1] + blk_s[2] + blk_s[3];
        atomicAdd((unsigned long long*)&g_acc, (unsigned long long)bs);
        __threadfence();
        unsigned int done = atomicAdd(&g_done, 1u);
        if (done == FIN_BLOCKS - 1) {
            long long tot = *(volatile long long*)&g_acc;
            out[0] = (float)((double)tot * (1.0 / 4294967296.0) * (1.0 / (double)B));
        }
    }
}

// ---------------- launch ----------------
extern "C" void kernel_launch(void* const* d_in, const int* in_sizes, int n_in,
                              void* d_out, int out_size)
{
    const int*   center_id   = (const int*)d_in[0];
    const int*   context_ids = (const int*)d_in[1];
    const float* epsilon     = (const float*)d_in[2];
    const float* emb         = (const float*)d_in[3];
    const float* prior_means = (const float*)d_in[4];
    const float* prior_vars  = (const float*)d_in[5];
    const float* W_enc       = (const float*)d_in[6];
    const float* b_enc       = (const float*)d_in[7];
    const float* W_mean      = (const float*)d_in[8];
    const float* b_mean      = (const float*)d_in[9];
    const float* W_var       = (const float*)d_in[10];
    const float* b_var       = (const float*)d_in[11];
    const float* W_vocab     = (const float*)d_in[12];
    const float* b_vocab     = (const float*)d_in[13];
    float* out = (float*)d_out;

    cudaFuncSetAttribute(encoder_kernel,
                         cudaFuncAttributeMaxDynamicSharedMemorySize, ESMEM);

    encoder_kernel<<<B / NB, 256, ESMEM>>>(center_id, context_ids, epsilon, emb,
                                           prior_means, prior_vars,
                                           W_enc, b_enc, W_mean, b_mean,
                                           W_var, b_var);

    dim3 grid2(NCHUNK, B / M_CTA);
    vocab_kernel<<<grid2, 256>>>(W_vocab, b_vocab);

    finalize_rows<<<FIN_BLOCKS, 128>>>(W_vocab, b_vocab, context_ids, out);
}